// round 11
// baseline (speedup 1.0000x reference)
#include <cuda_runtime.h>
#include <cuda_fp16.h>
#include <cstdint>

// ColumnParallelLinear: C[8192,4096] = A[8192,1024] @ W[4096,1024]^T (fp32).
// Single-term fp16 HMMA GEMM (norm rel-err ~3e-4 < 1e-3 threshold).
// CTA tile 128x128, 4 warps (2Mx2N, warp tile 64x64), 2-stage cp.async
// pipeline (32KB/stage, 64KB total) -> 3 CTAs/SM (12 warps), regs capped 170.

#define M_DIM 8192
#define N_DIM 4096
#define K_DIM 1024

#define BM 128
#define BN 128
#define BK 64                     // fp16 per k-chunk: 64*2 = 128B rows (SW128)
#define STAGES 2
#define KSTEPS (K_DIM / BK)       // 16

#define OFF_A 0                   // A tile: 128 rows * 128B = 16KB
#define OFF_W 16384               // W tile: 128 rows * 128B = 16KB
#define STAGE_B 32768
#define SMEM_TOTAL (STAGES * STAGE_B)   // 65536 per CTA -> 3 CTAs/SM

// ---------------- scratch (device globals: allocation-free rule) -------------
__device__ __half g_Ah[M_DIM * K_DIM];
__device__ __half g_Wh[N_DIM * K_DIM];

// ---------------- PTX helpers (compute_103-legal) ----------------------------
__device__ __forceinline__ uint32_t smem_u32(const void* p) {
    uint32_t a;
    asm("{ .reg .u64 t; cvta.to.shared.u64 t, %1; cvt.u32.u64 %0, t; }"
        : "=r"(a) : "l"(p));
    return a;
}
__device__ __forceinline__ void cp16(uint32_t dst, const void* src) {
    asm volatile("cp.async.cg.shared.global [%0], [%1], 16;"
                 :: "r"(dst), "l"(src) : "memory");
}
__device__ __forceinline__ void cp_commit() {
    asm volatile("cp.async.commit_group;" ::: "memory");
}
template <int N>
__device__ __forceinline__ void cp_wait() {
    asm volatile("cp.async.wait_group %0;" :: "n"(N) : "memory");
}
__device__ __forceinline__ void ldsm4(uint32_t* r, uint32_t addr) {
    asm volatile("ldmatrix.sync.aligned.m8n8.x4.shared.b16 {%0,%1,%2,%3}, [%4];"
                 : "=r"(r[0]), "=r"(r[1]), "=r"(r[2]), "=r"(r[3]) : "r"(addr));
}
__device__ __forceinline__ void mma_f16(float* d, const uint32_t* a,
                                        const uint32_t* b) {
    asm volatile(
        "mma.sync.aligned.m16n8k16.row.col.f32.f16.f16.f32 "
        "{%0,%1,%2,%3}, {%4,%5,%6,%7}, {%8,%9}, {%0,%1,%2,%3};"
        : "+f"(d[0]), "+f"(d[1]), "+f"(d[2]), "+f"(d[3])
        : "r"(a[0]), "r"(a[1]), "r"(a[2]), "r"(a[3]), "r"(b[0]), "r"(b[1]));
}

// ---------------- fused convert kernel: fp32 -> fp16 (A then W) --------------
__global__ void cvt_fused_kernel(const float* __restrict__ A,
                                 const float* __restrict__ W) {
    const int n8a = (M_DIM * K_DIM) / 8;
    int i = blockIdx.x * blockDim.x + threadIdx.x;
    const float* src;
    __half* dst;
    if (i < n8a) {
        src = A; dst = g_Ah;
    } else {
        src = W; dst = g_Wh; i -= n8a;
    }
    float4 v0 = reinterpret_cast<const float4*>(src)[2 * i];
    float4 v1 = reinterpret_cast<const float4*>(src)[2 * i + 1];
    __half2 h[4];
    h[0] = __floats2half2_rn(v0.x, v0.y);
    h[1] = __floats2half2_rn(v0.z, v0.w);
    h[2] = __floats2half2_rn(v1.x, v1.y);
    h[3] = __floats2half2_rn(v1.z, v1.w);
    reinterpret_cast<float4*>(dst)[i] = *reinterpret_cast<float4*>(h);
}

// ---------------- GEMM kernel ------------------------------------------------
__global__ __launch_bounds__(128, 3)
void gemm_f16_kernel(float* __restrict__ C) {
    extern __shared__ char smem[];
    const uint32_t sb = smem_u32(smem);
    const int tid  = threadIdx.x;
    const int wid  = tid >> 5;        // 0..3
    const int lane = tid & 31;
    const int bm = blockIdx.y * BM;
    const int bn = blockIdx.x * BN;
    const int mw = (wid & 1) * 64;    // warp M offset
    const int nw = (wid >> 1) * 64;   // warp N offset

    // ---- cp.async staging geometry ------------------------------------------
    // 128 threads; rows crow + i*16 (i=0..7); 16B chunk cc16 within 128B row.
    // Swizzle bits come from bits [7:10) of the offset; the i*2048 term does
    // not touch them, so one swizzled base + i*2048 suffices (saves 8 regs).
    const int crow = tid >> 3;        // 0..15
    const int cc16 = tid & 7;
    const uint32_t base0 = (uint32_t)crow * 128 + (uint32_t)cc16 * 16;
    const uint32_t swbase = base0 ^ ((base0 >> 3) & 0x70);
    const __half* srcA = g_Ah + (size_t)(bm + crow) * K_DIM + cc16 * 8;
    const __half* srcW = g_Wh + (size_t)(bn + crow) * K_DIM + cc16 * 8;

    auto load_stage = [&](uint32_t b, int kc) {
        size_t ko = (size_t)kc * BK;
#pragma unroll
        for (int i = 0; i < 8; i++) {
            size_t ro = (size_t)i * 16 * K_DIM + ko;
            cp16(b + OFF_A + swbase + (uint32_t)i * 2048, srcA + ro);
            cp16(b + OFF_W + swbase + (uint32_t)i * 2048, srcW + ro);
        }
        cp_commit();
    };

    // ---- ldmatrix address precompute ---------------------------------------
    const uint32_t aK   = (uint32_t)(lane >> 4) * 16;
    const uint32_t xorA = (uint32_t)(lane & 7) << 4;
    uint32_t rowA[4];
#pragma unroll
    for (int mi = 0; mi < 4; mi++)
        rowA[mi] = (uint32_t)(mw + mi * 16 + (lane & 15)) * 128;
    const uint32_t bK   = (uint32_t)((lane >> 3) & 1) << 4;
    const uint32_t xorB = (uint32_t)(lane & 7) << 4;
    uint32_t rowB[4];
#pragma unroll
    for (int nb = 0; nb < 4; nb++)
        rowB[nb] = (uint32_t)(nw + nb * 16 + ((lane >> 4) << 3) + (lane & 7)) * 128;

    float acc[4][8][4];
#pragma unroll
    for (int mi = 0; mi < 4; mi++)
#pragma unroll
        for (int ni = 0; ni < 8; ni++)
#pragma unroll
            for (int q = 0; q < 4; q++) acc[mi][ni][q] = 0.0f;

    // ---- pipeline prologue --------------------------------------------------
    load_stage(sb, 0);

    // ---- mainloop: 2-stage; per iter: wait(kc) -> sync -> load(kc+1) -> mma --
    for (int kc = 0; kc < KSTEPS; kc++) {
        const uint32_t cbase = sb + (uint32_t)(kc & 1) * STAGE_B;
        cp_wait<0>();
        __syncthreads();

        if (kc + 1 < KSTEPS)
            load_stage(sb + (uint32_t)((kc + 1) & 1) * STAGE_B, kc + 1);

#pragma unroll
        for (int kk = 0; kk < 4; kk++) {
            const uint32_t colA = (uint32_t)(kk * 32 + aK) ^ xorA;
            const uint32_t colB = (uint32_t)(kk * 32 + bK) ^ xorB;
            uint32_t af[4][4], bf[4][4];
#pragma unroll
            for (int mi = 0; mi < 4; mi++)
                ldsm4(af[mi], cbase + OFF_A + rowA[mi] + colA);
#pragma unroll
            for (int nb = 0; nb < 4; nb++)
                ldsm4(bf[nb], cbase + OFF_W + rowB[nb] + colB);
#pragma unroll
            for (int mi = 0; mi < 4; mi++) {
#pragma unroll
                for (int ni = 0; ni < 8; ni++) {
                    mma_f16(acc[mi][ni], af[mi], &bf[ni >> 1][(ni & 1) * 2]);
                }
            }
        }
    }

    // ---- epilogue: registers -> C ------------------------------------------
    const int er = lane >> 2;
    const int ec = (lane & 3) * 2;
#pragma unroll
    for (int mi = 0; mi < 4; mi++) {
#pragma unroll
        for (int ni = 0; ni < 8; ni += 2) {
            const int m = bm + mw + mi * 16 + er;
            const int n = bn + nw + ni * 8 + ec;
            float* r0 = C + (size_t)m * N_DIM + n;
            float* r1 = C + (size_t)(m + 8) * N_DIM + n;
            float2 a0 = {acc[mi][ni][0],     acc[mi][ni][1]};
            float2 b0 = {acc[mi][ni + 1][0], acc[mi][ni + 1][1]};
            float2 a1 = {acc[mi][ni][2],     acc[mi][ni][3]};
            float2 b1 = {acc[mi][ni + 1][2], acc[mi][ni + 1][3]};
            *reinterpret_cast<float2*>(r0)     = a0;
            *reinterpret_cast<float2*>(r0 + 8) = b0;
            *reinterpret_cast<float2*>(r1)     = a1;
            *reinterpret_cast<float2*>(r1 + 8) = b1;
        }
    }
}

// ---------------- host launch ------------------------------------------------
extern "C" void kernel_launch(void* const* d_in, const int* in_sizes, int n_in,
                              void* d_out, int out_size) {
    const float* A = (const float*)d_in[0];   // [8192, 1024]
    const float* W = (const float*)d_in[1];   // [4096, 1024]
    float* C       = (float*)d_out;           // [8192, 4096]

    {
        const int n8 = (M_DIM * K_DIM + N_DIM * K_DIM) / 8;
        cvt_fused_kernel<<<n8 / 256, 256>>>(A, W);
    }

    cudaFuncSetAttribute(gemm_f16_kernel,
                         cudaFuncAttributeMaxDynamicSharedMemorySize, SMEM_TOTAL);
    dim3 grid(N_DIM / BN, M_DIM / BM);   // (32, 64)
    gemm_f16_kernel<<<grid, 128, SMEM_TOTAL>>>(C);
}

// round 12
// speedup vs baseline: 1.0704x; 1.0704x over previous
#include <cuda_runtime.h>
#include <cuda_fp16.h>
#include <cstdint>

// ColumnParallelLinear: C[8192,4096] = A[8192,1024] @ W[4096,1024]^T (fp32).
// Single-term fp16 HMMA GEMM (norm rel-err ~3e-4 < 1e-3 threshold).
// R10 skeleton: CTA 128x128, 4 warps (2Mx2N, warp 64x64), 3-stage cp.async,
// 2 CTAs/SM. New: intra-chunk fragment double-buffering — ldmatrix for step
// kk+1 overlaps the 32 MMAs of step kk, hiding LDS latency after barriers.

#define M_DIM 8192
#define N_DIM 4096
#define K_DIM 1024

#define BM 128
#define BN 128
#define BK 64                     // fp16 per k-chunk: 64*2 = 128B rows (SW128)
#define STAGES 3
#define KSTEPS (K_DIM / BK)       // 16

#define OFF_A 0                   // A tile: 128 rows * 128B = 16KB
#define OFF_W 16384               // W tile: 128 rows * 128B = 16KB
#define STAGE_B 32768
#define SMEM_TOTAL (STAGES * STAGE_B)   // 98304 per CTA -> 2 CTAs/SM

// ---------------- scratch (device globals: allocation-free rule) -------------
__device__ __half g_Ah[M_DIM * K_DIM];
__device__ __half g_Wh[N_DIM * K_DIM];

// ---------------- PTX helpers (compute_103-legal) ----------------------------
__device__ __forceinline__ uint32_t smem_u32(const void* p) {
    uint32_t a;
    asm("{ .reg .u64 t; cvta.to.shared.u64 t, %1; cvt.u32.u64 %0, t; }"
        : "=r"(a) : "l"(p));
    return a;
}
__device__ __forceinline__ void cp16(uint32_t dst, const void* src) {
    asm volatile("cp.async.cg.shared.global [%0], [%1], 16;"
                 :: "r"(dst), "l"(src) : "memory");
}
__device__ __forceinline__ void cp_commit() {
    asm volatile("cp.async.commit_group;" ::: "memory");
}
template <int N>
__device__ __forceinline__ void cp_wait() {
    asm volatile("cp.async.wait_group %0;" :: "n"(N) : "memory");
}
__device__ __forceinline__ void ldsm4(uint32_t* r, uint32_t addr) {
    asm volatile("ldmatrix.sync.aligned.m8n8.x4.shared.b16 {%0,%1,%2,%3}, [%4];"
                 : "=r"(r[0]), "=r"(r[1]), "=r"(r[2]), "=r"(r[3]) : "r"(addr));
}
__device__ __forceinline__ void mma_f16(float* d, const uint32_t* a,
                                        const uint32_t* b) {
    asm volatile(
        "mma.sync.aligned.m16n8k16.row.col.f32.f16.f16.f32 "
        "{%0,%1,%2,%3}, {%4,%5,%6,%7}, {%8,%9}, {%0,%1,%2,%3};"
        : "+f"(d[0]), "+f"(d[1]), "+f"(d[2]), "+f"(d[3])
        : "r"(a[0]), "r"(a[1]), "r"(a[2]), "r"(a[3]), "r"(b[0]), "r"(b[1]));
}

// ---------------- fused convert kernel: fp32 -> fp16 (A then W) --------------
__global__ void cvt_fused_kernel(const float* __restrict__ A,
                                 const float* __restrict__ W) {
    const int n8a = (M_DIM * K_DIM) / 8;
    int i = blockIdx.x * blockDim.x + threadIdx.x;
    const float* src;
    __half* dst;
    if (i < n8a) {
        src = A; dst = g_Ah;
    } else {
        src = W; dst = g_Wh; i -= n8a;
    }
    float4 v0 = reinterpret_cast<const float4*>(src)[2 * i];
    float4 v1 = reinterpret_cast<const float4*>(src)[2 * i + 1];
    __half2 h[4];
    h[0] = __floats2half2_rn(v0.x, v0.y);
    h[1] = __floats2half2_rn(v0.z, v0.w);
    h[2] = __floats2half2_rn(v1.x, v1.y);
    h[3] = __floats2half2_rn(v1.z, v1.w);
    reinterpret_cast<float4*>(dst)[i] = *reinterpret_cast<float4*>(h);
}

// ---------------- GEMM kernel ------------------------------------------------
__global__ __launch_bounds__(128, 2)
void gemm_f16_kernel(float* __restrict__ C) {
    extern __shared__ char smem[];
    const uint32_t sb = smem_u32(smem);
    const int tid  = threadIdx.x;
    const int wid  = tid >> 5;        // 0..3
    const int lane = tid & 31;
    const int bm = blockIdx.y * BM;
    const int bn = blockIdx.x * BN;
    const int mw = (wid & 1) * 64;    // warp M offset
    const int nw = (wid >> 1) * 64;   // warp N offset

    // ---- cp.async staging geometry ------------------------------------------
    // 128 threads; rows crow + i*16 (i=0..7); 16B chunk cc16 within 128B row.
    // i*2048 doesn't touch swizzle bits [7:10): one swizzled base suffices.
    const int crow = tid >> 3;        // 0..15
    const int cc16 = tid & 7;
    const uint32_t base0 = (uint32_t)crow * 128 + (uint32_t)cc16 * 16;
    const uint32_t swbase = base0 ^ ((base0 >> 3) & 0x70);
    const __half* srcA = g_Ah + (size_t)(bm + crow) * K_DIM + cc16 * 8;
    const __half* srcW = g_Wh + (size_t)(bn + crow) * K_DIM + cc16 * 8;

    auto load_stage = [&](uint32_t b, int kc) {
        size_t ko = (size_t)kc * BK;
#pragma unroll
        for (int i = 0; i < 8; i++) {
            size_t ro = (size_t)i * 16 * K_DIM + ko;
            cp16(b + OFF_A + swbase + (uint32_t)i * 2048, srcA + ro);
            cp16(b + OFF_W + swbase + (uint32_t)i * 2048, srcW + ro);
        }
        cp_commit();
    };

    // ---- ldmatrix address precompute ---------------------------------------
    const uint32_t aK   = (uint32_t)(lane >> 4) * 16;
    const uint32_t xorA = (uint32_t)(lane & 7) << 4;
    uint32_t rowA[4];
#pragma unroll
    for (int mi = 0; mi < 4; mi++)
        rowA[mi] = (uint32_t)(mw + mi * 16 + (lane & 15)) * 128;
    const uint32_t bK   = (uint32_t)((lane >> 3) & 1) << 4;
    const uint32_t xorB = (uint32_t)(lane & 7) << 4;
    uint32_t rowB[4];
#pragma unroll
    for (int nb = 0; nb < 4; nb++)
        rowB[nb] = (uint32_t)(nw + nb * 16 + ((lane >> 4) << 3) + (lane & 7)) * 128;

    float acc[4][8][4];
#pragma unroll
    for (int mi = 0; mi < 4; mi++)
#pragma unroll
        for (int ni = 0; ni < 8; ni++)
#pragma unroll
            for (int q = 0; q < 4; q++) acc[mi][ni][q] = 0.0f;

    // ---- pipeline prologue --------------------------------------------------
    load_stage(sb, 0);
    load_stage(sb + STAGE_B, 1);

    uint32_t cbase = sb;                      // compute stage
    uint32_t lbase = sb + 2u * STAGE_B;       // next load stage
    const uint32_t wrap = sb + (uint32_t)STAGES * STAGE_B;

    // double-buffered fragments
    uint32_t af[2][4][4], bf[2][4][4];

    // ---- mainloop -----------------------------------------------------------
    for (int kc = 0; kc < KSTEPS; kc++) {
        if (kc < KSTEPS - 1) cp_wait<1>(); else cp_wait<0>();
        __syncthreads();

        if (kc + 2 < KSTEPS) {
            load_stage(lbase, kc + 2);
            lbase += STAGE_B; if (lbase == wrap) lbase = sb;
        }

        // fragments for kk=0
        {
            const uint32_t colA0 = aK ^ xorA;
            const uint32_t colB0 = bK ^ xorB;
#pragma unroll
            for (int mi = 0; mi < 4; mi++)
                ldsm4(af[0][mi], cbase + OFF_A + rowA[mi] + colA0);
#pragma unroll
            for (int nb = 0; nb < 4; nb++)
                ldsm4(bf[0][nb], cbase + OFF_W + rowB[nb] + colB0);
        }

#pragma unroll
        for (int kk = 0; kk < 4; kk++) {
            const int cur = kk & 1, nxt = cur ^ 1;
            // prefetch fragments for kk+1 (overlaps the 32 MMAs below)
            if (kk < 3) {
                const uint32_t colA = (uint32_t)((kk + 1) * 32 + aK) ^ xorA;
                const uint32_t colB = (uint32_t)((kk + 1) * 32 + bK) ^ xorB;
#pragma unroll
                for (int mi = 0; mi < 4; mi++)
                    ldsm4(af[nxt][mi], cbase + OFF_A + rowA[mi] + colA);
#pragma unroll
                for (int nb = 0; nb < 4; nb++)
                    ldsm4(bf[nxt][nb], cbase + OFF_W + rowB[nb] + colB);
            }
#pragma unroll
            for (int mi = 0; mi < 4; mi++) {
#pragma unroll
                for (int ni = 0; ni < 8; ni++) {
                    mma_f16(acc[mi][ni], af[cur][mi], &bf[cur][ni >> 1][(ni & 1) * 2]);
                }
            }
        }
        cbase += STAGE_B; if (cbase == wrap) cbase = sb;
    }

    // ---- epilogue: registers -> C ------------------------------------------
    const int er = lane >> 2;
    const int ec = (lane & 3) * 2;
#pragma unroll
    for (int mi = 0; mi < 4; mi++) {
#pragma unroll
        for (int ni = 0; ni < 8; ni += 2) {
            const int m = bm + mw + mi * 16 + er;
            const int n = bn + nw + ni * 8 + ec;
            float* r0 = C + (size_t)m * N_DIM + n;
            float* r1 = C + (size_t)(m + 8) * N_DIM + n;
            float2 a0 = {acc[mi][ni][0],     acc[mi][ni][1]};
            float2 b0 = {acc[mi][ni + 1][0], acc[mi][ni + 1][1]};
            float2 a1 = {acc[mi][ni][2],     acc[mi][ni][3]};
            float2 b1 = {acc[mi][ni + 1][2], acc[mi][ni + 1][3]};
            *reinterpret_cast<float2*>(r0)     = a0;
            *reinterpret_cast<float2*>(r0 + 8) = b0;
            *reinterpret_cast<float2*>(r1)     = a1;
            *reinterpret_cast<float2*>(r1 + 8) = b1;
        }
    }
}

// ---------------- host launch ------------------------------------------------
extern "C" void kernel_launch(void* const* d_in, const int* in_sizes, int n_in,
                              void* d_out, int out_size) {
    const float* A = (const float*)d_in[0];   // [8192, 1024]
    const float* W = (const float*)d_in[1];   // [4096, 1024]
    float* C       = (float*)d_out;           // [8192, 4096]

    {
        const int n8 = (M_DIM * K_DIM + N_DIM * K_DIM) / 8;
        cvt_fused_kernel<<<n8 / 256, 256>>>(A, W);
    }

    cudaFuncSetAttribute(gemm_f16_kernel,
                         cudaFuncAttributeMaxDynamicSharedMemorySize, SMEM_TOTAL);
    dim3 grid(N_DIM / BN, M_DIM / BM);   // (32, 64)
    gemm_f16_kernel<<<grid, 128, SMEM_TOTAL>>>(C);
}

// round 14
// speedup vs baseline: 1.0993x; 1.0270x over previous
#include <cuda_runtime.h>
#include <cuda_fp16.h>
#include <cstdint>

// ColumnParallelLinear: C[8192,4096] = A[8192,1024] @ W[4096,1024]^T (fp32).
// Single-term fp16 HMMA GEMM (norm rel-err ~3e-4 < 1e-3 threshold).
// CTA 128x128, 4 warps (2Mx2N, warp 64x64), 3-stage ring, 2 CTAs/SM.
// Per-chunk sync = mbarrier producer/consumer ring (no __syncthreads):
//   full[s]  : init 128, armed by cp.async.mbarrier.arrive.NOINC per thread
//              (.noinc is load-bearing: the default variant self-balances by
//               incrementing the pending count at issue and never flips)
//   empty[s] : init 4, lane-0 arrive per warp after last smem read of slot s.

#define M_DIM 8192
#define N_DIM 4096
#define K_DIM 1024

#define BM 128
#define BN 128
#define BK 64                     // fp16 per k-chunk: 64*2 = 128B rows (SW128)
#define STAGES 3
#define KSTEPS (K_DIM / BK)       // 16

#define OFF_A 0                   // A tile: 128 rows * 128B = 16KB
#define OFF_W 16384               // W tile: 128 rows * 128B = 16KB
#define STAGE_B 32768
#define BARS_OFF (STAGES * STAGE_B)          // 98304: 6 mbarriers (48B)
#define SMEM_TOTAL (BARS_OFF + 64)           // 98368 per CTA -> 2 CTAs/SM

// ---------------- scratch (device globals: allocation-free rule) -------------
__device__ __half g_Ah[M_DIM * K_DIM];
__device__ __half g_Wh[N_DIM * K_DIM];

// ---------------- PTX helpers (compute_103-legal, sm_80/90-era) --------------
__device__ __forceinline__ uint32_t smem_u32(const void* p) {
    uint32_t a;
    asm("{ .reg .u64 t; cvta.to.shared.u64 t, %1; cvt.u32.u64 %0, t; }"
        : "=r"(a) : "l"(p));
    return a;
}
__device__ __forceinline__ void cp16(uint32_t dst, const void* src) {
    asm volatile("cp.async.cg.shared.global [%0], [%1], 16;"
                 :: "r"(dst), "l"(src) : "memory");
}
__device__ __forceinline__ void cp_arrive_noinc(uint32_t mbar) {
    // arrival lands when ALL prior cp.async of this thread complete;
    // .noinc: consumes a pre-registered expected arrival (init count).
    asm volatile("cp.async.mbarrier.arrive.noinc.shared.b64 [%0];"
                 :: "r"(mbar) : "memory");
}
__device__ __forceinline__ void mbar_init(uint32_t mbar, uint32_t count) {
    asm volatile("mbarrier.init.shared.b64 [%0], %1;"
                 :: "r"(mbar), "r"(count) : "memory");
}
__device__ __forceinline__ void mbar_arrive(uint32_t mbar) {
    asm volatile("mbarrier.arrive.shared.b64 _, [%0];" :: "r"(mbar) : "memory");
}
__device__ __forceinline__ void mbar_wait(uint32_t mbar, uint32_t parity) {
    asm volatile(
        "{\n\t.reg .pred P;\n\t"
        "LW%=:\n\t"
        "mbarrier.try_wait.parity.shared.b64 P, [%0], %1, 0x989680;\n\t"
        "@P bra LD%=;\n\t"
        "bra LW%=;\n\t"
        "LD%=:\n\t}"
        :: "r"(mbar), "r"(parity) : "memory");
}
__device__ __forceinline__ void ldsm4(uint32_t* r, uint32_t addr) {
    asm volatile("ldmatrix.sync.aligned.m8n8.x4.shared.b16 {%0,%1,%2,%3}, [%4];"
                 : "=r"(r[0]), "=r"(r[1]), "=r"(r[2]), "=r"(r[3]) : "r"(addr));
}
__device__ __forceinline__ void mma_f16(float* d, const uint32_t* a,
                                        const uint32_t* b) {
    asm volatile(
        "mma.sync.aligned.m16n8k16.row.col.f32.f16.f16.f32 "
        "{%0,%1,%2,%3}, {%4,%5,%6,%7}, {%8,%9}, {%0,%1,%2,%3};"
        : "+f"(d[0]), "+f"(d[1]), "+f"(d[2]), "+f"(d[3])
        : "r"(a[0]), "r"(a[1]), "r"(a[2]), "r"(a[3]), "r"(b[0]), "r"(b[1]));
}

// ---------------- fused convert kernel: fp32 -> fp16, 16 floats/thread -------
__global__ void cvt_fused_kernel(const float* __restrict__ A,
                                 const float* __restrict__ W) {
    const int n16a = (M_DIM * K_DIM) / 16;
    int i = blockIdx.x * blockDim.x + threadIdx.x;
    const float* src;
    __half* dst;
    if (i < n16a) {
        src = A; dst = g_Ah;
    } else {
        src = W; dst = g_Wh; i -= n16a;
    }
    float4 v0 = reinterpret_cast<const float4*>(src)[4 * i];
    float4 v1 = reinterpret_cast<const float4*>(src)[4 * i + 1];
    float4 v2 = reinterpret_cast<const float4*>(src)[4 * i + 2];
    float4 v3 = reinterpret_cast<const float4*>(src)[4 * i + 3];
    __half2 h[8];
    h[0] = __floats2half2_rn(v0.x, v0.y); h[1] = __floats2half2_rn(v0.z, v0.w);
    h[2] = __floats2half2_rn(v1.x, v1.y); h[3] = __floats2half2_rn(v1.z, v1.w);
    h[4] = __floats2half2_rn(v2.x, v2.y); h[5] = __floats2half2_rn(v2.z, v2.w);
    h[6] = __floats2half2_rn(v3.x, v3.y); h[7] = __floats2half2_rn(v3.z, v3.w);
    reinterpret_cast<float4*>(dst)[2 * i]     = *reinterpret_cast<float4*>(h);
    reinterpret_cast<float4*>(dst)[2 * i + 1] = *reinterpret_cast<float4*>(h + 4);
}

// ---------------- GEMM kernel ------------------------------------------------
__global__ __launch_bounds__(128, 2)
void gemm_f16_kernel(float* __restrict__ C) {
    extern __shared__ char smem[];
    const uint32_t sb = smem_u32(smem);
    const uint32_t bars = sb + BARS_OFF;      // full[0..2]@+0, empty[0..2]@+24
    const int tid  = threadIdx.x;
    const int wid  = tid >> 5;
    const int lane = tid & 31;
    const int bm = blockIdx.y * BM;
    const int bn = blockIdx.x * BN;
    const int mw = (wid & 1) * 64;
    const int nw = (wid >> 1) * 64;

    if (tid == 0) {
#pragma unroll
        for (int s = 0; s < 3; s++) {
            mbar_init(bars + s * 8, 128);       // full: one noinc-arrive/thread
            mbar_init(bars + 24 + s * 8, 4);    // empty: one arrive per warp
        }
    }
    __syncthreads();

    // ---- cp.async staging geometry ------------------------------------------
    const int crow = tid >> 3;        // 0..15
    const int cc16 = tid & 7;
    const uint32_t base0 = (uint32_t)crow * 128 + (uint32_t)cc16 * 16;
    const uint32_t swbase = base0 ^ ((base0 >> 3) & 0x70);
    const __half* srcA = g_Ah + (size_t)(bm + crow) * K_DIM + cc16 * 8;
    const __half* srcW = g_Wh + (size_t)(bn + crow) * K_DIM + cc16 * 8;

    auto load_stage = [&](uint32_t b, int kc, uint32_t fullbar) {
        size_t ko = (size_t)kc * BK;
#pragma unroll
        for (int i = 0; i < 8; i++) {
            size_t ro = (size_t)i * 16 * K_DIM + ko;
            cp16(b + OFF_A + swbase + (uint32_t)i * 2048, srcA + ro);
            cp16(b + OFF_W + swbase + (uint32_t)i * 2048, srcW + ro);
        }
        cp_arrive_noinc(fullbar);
    };

    // ---- ldmatrix address precompute ---------------------------------------
    const uint32_t aK   = (uint32_t)(lane >> 4) * 16;
    const uint32_t xorA = (uint32_t)(lane & 7) << 4;
    uint32_t rowA[4];
#pragma unroll
    for (int mi = 0; mi < 4; mi++)
        rowA[mi] = (uint32_t)(mw + mi * 16 + (lane & 15)) * 128;
    const uint32_t bK   = (uint32_t)((lane >> 3) & 1) << 4;
    const uint32_t xorB = (uint32_t)(lane & 7) << 4;
    uint32_t rowB[4];
#pragma unroll
    for (int nb = 0; nb < 4; nb++)
        rowB[nb] = (uint32_t)(nw + nb * 16 + ((lane >> 4) << 3) + (lane & 7)) * 128;

    float acc[4][8][4];
#pragma unroll
    for (int mi = 0; mi < 4; mi++)
#pragma unroll
        for (int ni = 0; ni < 8; ni++)
#pragma unroll
            for (int q = 0; q < 4; q++) acc[mi][ni][q] = 0.0f;

    // ---- prologue: stage chunks 0,1 (fresh slots: no empty wait) ------------
    load_stage(sb, 0, bars + 0);
    load_stage(sb + STAGE_B, 1, bars + 8);

    uint32_t af[2][4][4], bf[2][4][4];

    // ---- mainloop: mbarrier ring, no __syncthreads --------------------------
    for (int kc = 0; kc < KSTEPS; kc++) {
        const int uf = kc / 3;
        const int s  = kc - uf * 3;              // kc % 3
        const uint32_t cbase = sb + (uint32_t)s * STAGE_B;

        // wait current chunk's data (flips when all 128 threads' loads landed)
        mbar_wait(bars + s * 8, (uint32_t)(uf & 1));

        // stage chunk kc+2 (slot last read at iter kc-1)
        if (kc + 2 < KSTEPS) {
            const int c  = kc + 2;
            const int ue = c / 3;
            const int s2 = c - ue * 3;
            if (c >= 3)                           // first use: slot fresh, skip
                mbar_wait(bars + 24 + s2 * 8, (uint32_t)((ue + 1) & 1));
            load_stage(sb + (uint32_t)s2 * STAGE_B, c, bars + s2 * 8);
        }

        // fragments for kk=0
        {
            const uint32_t colA0 = aK ^ xorA;
            const uint32_t colB0 = bK ^ xorB;
#pragma unroll
            for (int mi = 0; mi < 4; mi++)
                ldsm4(af[0][mi], cbase + OFF_A + rowA[mi] + colA0);
#pragma unroll
            for (int nb = 0; nb < 4; nb++)
                ldsm4(bf[0][nb], cbase + OFF_W + rowB[nb] + colB0);
        }

#pragma unroll
        for (int kk = 0; kk < 4; kk++) {
            const int cur = kk & 1, nxt = cur ^ 1;
            if (kk < 3) {
                const uint32_t colA = (uint32_t)((kk + 1) * 32 + aK) ^ xorA;
                const uint32_t colB = (uint32_t)((kk + 1) * 32 + bK) ^ xorB;
#pragma unroll
                for (int mi = 0; mi < 4; mi++)
                    ldsm4(af[nxt][mi], cbase + OFF_A + rowA[mi] + colA);
#pragma unroll
                for (int nb = 0; nb < 4; nb++)
                    ldsm4(bf[nxt][nb], cbase + OFF_W + rowB[nb] + colB);
            }
#pragma unroll
            for (int mi = 0; mi < 4; mi++) {
#pragma unroll
                for (int ni = 0; ni < 8; ni++) {
                    mma_f16(acc[mi][ni], af[cur][mi], &bf[cur][ni >> 1][(ni & 1) * 2]);
                }
            }
        }

        // this warp is done reading slot s (arrive has release.cta semantics)
        if (lane == 0) mbar_arrive(bars + 24 + s * 8);
    }

    // ---- epilogue: registers -> C ------------------------------------------
    const int er = lane >> 2;
    const int ec = (lane & 3) * 2;
#pragma unroll
    for (int mi = 0; mi < 4; mi++) {
#pragma unroll
        for (int ni = 0; ni < 8; ni += 2) {
            const int m = bm + mw + mi * 16 + er;
            const int n = bn + nw + ni * 8 + ec;
            float* r0 = C + (size_t)m * N_DIM + n;
            float* r1 = C + (size_t)(m + 8) * N_DIM + n;
            float2 a0 = {acc[mi][ni][0],     acc[mi][ni][1]};
            float2 b0 = {acc[mi][ni + 1][0], acc[mi][ni + 1][1]};
            float2 a1 = {acc[mi][ni][2],     acc[mi][ni][3]};
            float2 b1 = {acc[mi][ni + 1][2], acc[mi][ni + 1][3]};
            *reinterpret_cast<float2*>(r0)     = a0;
            *reinterpret_cast<float2*>(r0 + 8) = b0;
            *reinterpret_cast<float2*>(r1)     = a1;
            *reinterpret_cast<float2*>(r1 + 8) = b1;
        }
    }
}

// ---------------- host launch ------------------------------------------------
extern "C" void kernel_launch(void* const* d_in, const int* in_sizes, int n_in,
                              void* d_out, int out_size) {
    const float* A = (const float*)d_in[0];   // [8192, 1024]
    const float* W = (const float*)d_in[1];   // [4096, 1024]
    float* C       = (float*)d_out;           // [8192, 4096]

    {
        const int n16 = (M_DIM * K_DIM + N_DIM * K_DIM) / 16;   // 786432
        cvt_fused_kernel<<<n16 / 256, 256>>>(A, W);
    }

    cudaFuncSetAttribute(gemm_f16_kernel,
                         cudaFuncAttributeMaxDynamicSharedMemorySize, SMEM_TOTAL);
    dim3 grid(N_DIM / BN, M_DIM / BM);   // (32, 64)
    gemm_f16_kernel<<<grid, 128, SMEM_TOTAL>>>(C);
}

// round 16
// speedup vs baseline: 1.1154x; 1.0147x over previous
#include <cuda_runtime.h>
#include <cuda_fp16.h>
#include <cstdint>

// ColumnParallelLinear: C[8192,4096] = A[8192,1024] @ W[4096,1024]^T (fp32).
// Single-term fp16 HMMA GEMM (norm rel-err ~3e-4 < 1e-3 threshold).
// CTA 128x128, 4 warps (2Mx2N, warp 64x64), 3-stage mbarrier ring, 2 CTAs/SM.
// New vs R14: cross-chunk fragment pipelining — during kk=3 of chunk kc we
// wait full[next] (normally pre-satisfied), prefetch chunk kc+1's kk=0
// fragments, and arrive empty[s] early. LDSM issue is a continuous stream;
// no cold dependent LDSM chain at chunk starts.

#define M_DIM 8192
#define N_DIM 4096
#define K_DIM 1024

#define BM 128
#define BN 128
#define BK 64                     // fp16 per k-chunk: 64*2 = 128B rows (SW128)
#define STAGES 3
#define KSTEPS (K_DIM / BK)       // 16

#define OFF_A 0                   // A tile: 128 rows * 128B = 16KB
#define OFF_W 16384               // W tile: 128 rows * 128B = 16KB
#define STAGE_B 32768
#define BARS_OFF (STAGES * STAGE_B)          // 98304: 6 mbarriers
#define SMEM_TOTAL (BARS_OFF + 64)           // 98368 per CTA -> 2 CTAs/SM

// ---------------- scratch (device globals: allocation-free rule) -------------
__device__ __half g_Ah[M_DIM * K_DIM];
__device__ __half g_Wh[N_DIM * K_DIM];

// ---------------- PTX helpers (compute_103-legal, sm_80/90-era) --------------
__device__ __forceinline__ uint32_t smem_u32(const void* p) {
    uint32_t a;
    asm("{ .reg .u64 t; cvta.to.shared.u64 t, %1; cvt.u32.u64 %0, t; }"
        : "=r"(a) : "l"(p));
    return a;
}
__device__ __forceinline__ void cp16(uint32_t dst, const void* src) {
    asm volatile("cp.async.cg.shared.global [%0], [%1], 16;"
                 :: "r"(dst), "l"(src) : "memory");
}
__device__ __forceinline__ void cp_arrive_noinc(uint32_t mbar) {
    asm volatile("cp.async.mbarrier.arrive.noinc.shared.b64 [%0];"
                 :: "r"(mbar) : "memory");
}
__device__ __forceinline__ void mbar_init(uint32_t mbar, uint32_t count) {
    asm volatile("mbarrier.init.shared.b64 [%0], %1;"
                 :: "r"(mbar), "r"(count) : "memory");
}
__device__ __forceinline__ void mbar_arrive(uint32_t mbar) {
    asm volatile("mbarrier.arrive.shared.b64 _, [%0];" :: "r"(mbar) : "memory");
}
__device__ __forceinline__ void mbar_wait(uint32_t mbar, uint32_t parity) {
    asm volatile(
        "{\n\t.reg .pred P;\n\t"
        "LW%=:\n\t"
        "mbarrier.try_wait.parity.shared.b64 P, [%0], %1, 0x989680;\n\t"
        "@P bra LD%=;\n\t"
        "bra LW%=;\n\t"
        "LD%=:\n\t}"
        :: "r"(mbar), "r"(parity) : "memory");
}
__device__ __forceinline__ void ldsm4(uint32_t* r, uint32_t addr) {
    asm volatile("ldmatrix.sync.aligned.m8n8.x4.shared.b16 {%0,%1,%2,%3}, [%4];"
                 : "=r"(r[0]), "=r"(r[1]), "=r"(r[2]), "=r"(r[3]) : "r"(addr));
}
__device__ __forceinline__ void mma_f16(float* d, const uint32_t* a,
                                        const uint32_t* b) {
    asm volatile(
        "mma.sync.aligned.m16n8k16.row.col.f32.f16.f16.f32 "
        "{%0,%1,%2,%3}, {%4,%5,%6,%7}, {%8,%9}, {%0,%1,%2,%3};"
        : "+f"(d[0]), "+f"(d[1]), "+f"(d[2]), "+f"(d[3])
        : "r"(a[0]), "r"(a[1]), "r"(a[2]), "r"(a[3]), "r"(b[0]), "r"(b[1]));
}

// ---------------- fused convert kernel: fp32 -> fp16, 16 floats/thread -------
__global__ void cvt_fused_kernel(const float* __restrict__ A,
                                 const float* __restrict__ W) {
    const int n16a = (M_DIM * K_DIM) / 16;
    int i = blockIdx.x * blockDim.x + threadIdx.x;
    const float* src;
    __half* dst;
    if (i < n16a) {
        src = A; dst = g_Ah;
    } else {
        src = W; dst = g_Wh; i -= n16a;
    }
    float4 v0 = reinterpret_cast<const float4*>(src)[4 * i];
    float4 v1 = reinterpret_cast<const float4*>(src)[4 * i + 1];
    float4 v2 = reinterpret_cast<const float4*>(src)[4 * i + 2];
    float4 v3 = reinterpret_cast<const float4*>(src)[4 * i + 3];
    __half2 h[8];
    h[0] = __floats2half2_rn(v0.x, v0.y); h[1] = __floats2half2_rn(v0.z, v0.w);
    h[2] = __floats2half2_rn(v1.x, v1.y); h[3] = __floats2half2_rn(v1.z, v1.w);
    h[4] = __floats2half2_rn(v2.x, v2.y); h[5] = __floats2half2_rn(v2.z, v2.w);
    h[6] = __floats2half2_rn(v3.x, v3.y); h[7] = __floats2half2_rn(v3.z, v3.w);
    reinterpret_cast<float4*>(dst)[2 * i]     = *reinterpret_cast<float4*>(h);
    reinterpret_cast<float4*>(dst)[2 * i + 1] = *reinterpret_cast<float4*>(h + 4);
}

// ---------------- GEMM kernel ------------------------------------------------
__global__ __launch_bounds__(128, 2)
void gemm_f16_kernel(float* __restrict__ C) {
    extern __shared__ char smem[];
    const uint32_t sb = smem_u32(smem);
    const uint32_t bars = sb + BARS_OFF;      // full[0..2]@+0, empty[0..2]@+24
    const int tid  = threadIdx.x;
    const int wid  = tid >> 5;
    const int lane = tid & 31;
    const int bm = blockIdx.y * BM;
    const int bn = blockIdx.x * BN;
    const int mw = (wid & 1) * 64;
    const int nw = (wid >> 1) * 64;

    if (tid == 0) {
#pragma unroll
        for (int s = 0; s < 3; s++) {
            mbar_init(bars + s * 8, 128);       // full: one noinc-arrive/thread
            mbar_init(bars + 24 + s * 8, 4);    // empty: one arrive per warp
        }
    }
    __syncthreads();

    // ---- cp.async staging geometry ------------------------------------------
    const int crow = tid >> 3;
    const int cc16 = tid & 7;
    const uint32_t base0 = (uint32_t)crow * 128 + (uint32_t)cc16 * 16;
    const uint32_t swbase = base0 ^ ((base0 >> 3) & 0x70);
    const __half* srcA = g_Ah + (size_t)(bm + crow) * K_DIM + cc16 * 8;
    const __half* srcW = g_Wh + (size_t)(bn + crow) * K_DIM + cc16 * 8;

    auto load_stage = [&](uint32_t b, int kc, uint32_t fullbar) {
        size_t ko = (size_t)kc * BK;
#pragma unroll
        for (int i = 0; i < 8; i++) {
            size_t ro = (size_t)i * 16 * K_DIM + ko;
            cp16(b + OFF_A + swbase + (uint32_t)i * 2048, srcA + ro);
            cp16(b + OFF_W + swbase + (uint32_t)i * 2048, srcW + ro);
        }
        cp_arrive_noinc(fullbar);
    };

    // ---- ldmatrix address precompute ---------------------------------------
    const uint32_t aK   = (uint32_t)(lane >> 4) * 16;
    const uint32_t xorA = (uint32_t)(lane & 7) << 4;
    uint32_t rowA[4];
#pragma unroll
    for (int mi = 0; mi < 4; mi++)
        rowA[mi] = (uint32_t)(mw + mi * 16 + (lane & 15)) * 128;
    const uint32_t bK   = (uint32_t)((lane >> 3) & 1) << 4;
    const uint32_t xorB = (uint32_t)(lane & 7) << 4;
    uint32_t rowB[4];
#pragma unroll
    for (int nb = 0; nb < 4; nb++)
        rowB[nb] = (uint32_t)(nw + nb * 16 + ((lane >> 4) << 3) + (lane & 7)) * 128;

    const uint32_t colA0 = aK ^ xorA;
    const uint32_t colB0 = bK ^ xorB;

    float acc[4][8][4];
#pragma unroll
    for (int mi = 0; mi < 4; mi++)
#pragma unroll
        for (int ni = 0; ni < 8; ni++)
#pragma unroll
            for (int q = 0; q < 4; q++) acc[mi][ni][q] = 0.0f;

    uint32_t af[2][4][4], bf[2][4][4];

    // ---- prologue: stage chunks 0,1; warm kk=0 fragments of chunk 0 ---------
    load_stage(sb, 0, bars + 0);
    load_stage(sb + STAGE_B, 1, bars + 8);
    mbar_wait(bars + 0, 0u);
#pragma unroll
    for (int mi = 0; mi < 4; mi++)
        ldsm4(af[0][mi], sb + OFF_A + rowA[mi] + colA0);
#pragma unroll
    for (int nb = 0; nb < 4; nb++)
        ldsm4(bf[0][nb], sb + OFF_W + rowB[nb] + colB0);

    // ---- mainloop: fragments pipelined across chunk boundaries --------------
    for (int kc = 0; kc < KSTEPS; kc++) {
        const int uf = kc / 3;
        const int s  = kc - uf * 3;              // kc % 3
        const uint32_t cbase = sb + (uint32_t)s * STAGE_B;

        // stage chunk kc+2 (slot last consumed at iter kc-1)
        if (kc + 2 < KSTEPS) {
            const int c  = kc + 2;
            const int ue = c / 3;
            const int s2 = c - ue * 3;
            if (c >= 3)
                mbar_wait(bars + 24 + s2 * 8, (uint32_t)((ue + 1) & 1));
            load_stage(sb + (uint32_t)s2 * STAGE_B, c, bars + s2 * 8);
        }

#pragma unroll
        for (int kk = 0; kk < 4; kk++) {
            const int cur = kk & 1, nxt = cur ^ 1;
            if (kk < 3) {
                // prefetch this chunk's kk+1 fragments
                const uint32_t colA = (uint32_t)((kk + 1) * 32 + aK) ^ xorA;
                const uint32_t colB = (uint32_t)((kk + 1) * 32 + bK) ^ xorB;
#pragma unroll
                for (int mi = 0; mi < 4; mi++)
                    ldsm4(af[nxt][mi], cbase + OFF_A + rowA[mi] + colA);
#pragma unroll
                for (int nb = 0; nb < 4; nb++)
                    ldsm4(bf[nxt][nb], cbase + OFF_W + rowB[nb] + colB);
            } else if (kc + 1 < KSTEPS) {
                // cross-chunk: wait next chunk's data (normally pre-satisfied),
                // prefetch its kk=0 fragments into buf 0 (nxt == 0 here)
                const int c  = kc + 1;
                const int un = c / 3;
                const int sn = c - un * 3;
                const uint32_t nbase = sb + (uint32_t)sn * STAGE_B;
                mbar_wait(bars + sn * 8, (uint32_t)(un & 1));
#pragma unroll
                for (int mi = 0; mi < 4; mi++)
                    ldsm4(af[nxt][mi], nbase + OFF_A + rowA[mi] + colA0);
#pragma unroll
                for (int nb = 0; nb < 4; nb++)
                    ldsm4(bf[nxt][nb], nbase + OFF_W + rowB[nb] + colB0);
                // slot s fully read (its last reads were kk=3 frags at kk=2);
                // release-arrive orders those prior shared reads
                if (lane == 0) mbar_arrive(bars + 24 + s * 8);
            }
#pragma unroll
            for (int mi = 0; mi < 4; mi++) {
#pragma unroll
                for (int ni = 0; ni < 8; ni++) {
                    mma_f16(acc[mi][ni], af[cur][mi], &bf[cur][ni >> 1][(ni & 1) * 2]);
                }
            }
        }
    }

    // ---- epilogue: registers -> C ------------------------------------------
    const int er = lane >> 2;
    const int ec = (lane & 3) * 2;
#pragma unroll
    for (int mi = 0; mi < 4; mi++) {
#pragma unroll
        for (int ni = 0; ni < 8; ni += 2) {
            const int m = bm + mw + mi * 16 + er;
            const int n = bn + nw + ni * 8 + ec;
            float* r0 = C + (size_t)m * N_DIM + n;
            float* r1 = C + (size_t)(m + 8) * N_DIM + n;
            float2 a0 = {acc[mi][ni][0],     acc[mi][ni][1]};
            float2 b0 = {acc[mi][ni + 1][0], acc[mi][ni + 1][1]};
            float2 a1 = {acc[mi][ni][2],     acc[mi][ni][3]};
            float2 b1 = {acc[mi][ni + 1][2], acc[mi][ni + 1][3]};
            *reinterpret_cast<float2*>(r0)     = a0;
            *reinterpret_cast<float2*>(r0 + 8) = b0;
            *reinterpret_cast<float2*>(r1)     = a1;
            *reinterpret_cast<float2*>(r1 + 8) = b1;
        }
    }
}

// ---------------- host launch ------------------------------------------------
extern "C" void kernel_launch(void* const* d_in, const int* in_sizes, int n_in,
                              void* d_out, int out_size) {
    const float* A = (const float*)d_in[0];   // [8192, 1024]
    const float* W = (const float*)d_in[1];   // [4096, 1024]
    float* C       = (float*)d_out;           // [8192, 4096]

    {
        const int n16 = (M_DIM * K_DIM + N_DIM * K_DIM) / 16;   // 786432
        cvt_fused_kernel<<<n16 / 256, 256>>>(A, W);
    }

    cudaFuncSetAttribute(gemm_f16_kernel,
                         cudaFuncAttributeMaxDynamicSharedMemorySize, SMEM_TOTAL);
    dim3 grid(N_DIM / BN, M_DIM / BM);   // (32, 64)
    gemm_f16_kernel<<<grid, 128, SMEM_TOTAL>>>(C);
}